// round 1
// baseline (speedup 1.0000x reference)
#include <cuda_runtime.h>
#include <math.h>

#define SEQ    256
#define BATCH  256
#define KD     1024   // C_IN * R_IN
#define ND     1024   // C_OUT * R_OUT
#define MX     (SEQ * BATCH)

// Scratch (device globals; no runtime allocation allowed).
// g_gx: x-projections for all timesteps, per gate: [3][SEQ*BATCH][ND]  (768 MB)
// g_gh: h-projections for current timestep:        [3][BATCH][ND]      (3 MB)
static __device__ float g_gx[(size_t)3 * MX * ND];
static __device__ float g_gh[(size_t)3 * BATCH * ND];

typedef unsigned long long u64;

__device__ __forceinline__ u64 pack_dup(float v) {
    u64 r; asm("mov.b64 %0, {%1, %1};" : "=l"(r) : "f"(v)); return r;
}
__device__ __forceinline__ u64 pack2(float lo, float hi) {
    u64 r; asm("mov.b64 %0, {%1, %2};" : "=l"(r) : "f"(lo), "f"(hi)); return r;
}
__device__ __forceinline__ void unpack2(u64 v, float& lo, float& hi) {
    asm("mov.b64 {%0, %1}, %2;" : "=f"(lo), "=f"(hi) : "l"(v));
}
// Packed fp32x2 FMA: 2 FMAs per instruction (sm_100+). This is the only way
// to reach 128 FMA/cyc/SM on sm_103a (plain FFMA is rt=2 -> 64/cyc).
__device__ __forceinline__ void ffma2(u64& d, u64 a, u64 b) {
    asm("fma.rn.f32x2 %0, %1, %2, %0;" : "+l"(d) : "l"(a), "l"(b));
}

// C[g][m][n] = sum_k A[m][k] * W_g[n][k] + bias_g[n]
// A: [M][KD] row-major.  W: [ND][KD] row-major (K-contiguous, as given).
// blockIdx.z = gate g in {0:r, 1:u(z), 2:c}.
// IS_GX ? C = g_gx + g*MX*ND (M = MX) : C = g_gh + g*BATCH*ND (M = BATCH).
template<int BM, int BN, int BK, int THREADS, bool IS_GX>
__global__ __launch_bounds__(THREADS)
void gemm3(const float* __restrict__ A,
           const float* __restrict__ W0, const float* __restrict__ W1,
           const float* __restrict__ W2,
           const float* __restrict__ b0, const float* __restrict__ b1,
           const float* __restrict__ b2)
{
    constexpr int TM  = 8, TN = 8;
    constexpr int TX  = BN / TN;
    constexpr int TY  = BM / TM;
    static_assert(TX * TY == THREADS, "thread grid mismatch");
    constexpr int AF4 = BM * BK / 4 / THREADS;   // float4 loads per thread (A)
    constexpr int BF4 = BN * BK / 4 / THREADS;   // float4 loads per thread (B)
    constexpr int KB4 = BK / 4;

    __shared__ float As[BK][BM + 4];
    __shared__ float Bs[BK][BN + 4];

    const int g = blockIdx.z;
    const float* W    = (g == 0) ? W0 : (g == 1) ? W1 : W2;
    const float* bias = (g == 0) ? b0 : (g == 1) ? b1 : b2;
    float* C = IS_GX ? (g_gx + (size_t)g * ((size_t)MX * ND))
                     : (g_gh + (size_t)g * ((size_t)BATCH * ND));

    const int tid = threadIdx.x;
    const int tx  = tid % TX;
    const int ty  = tid / TX;
    const int m0  = blockIdx.x * BM;
    const int n0  = blockIdx.y * BN;

    const float* Ap = A + (size_t)m0 * KD;
    const float* Wp = W + (size_t)n0 * KD;

    float4 ar[AF4], br[BF4];

    // Prologue: stage first K-tile into registers.
    #pragma unroll
    for (int i = 0; i < AF4; i++) {
        int q = tid + i * THREADS;
        ar[i] = *(const float4*)(Ap + (size_t)(q / KB4) * KD + (q % KB4) * 4);
    }
    #pragma unroll
    for (int i = 0; i < BF4; i++) {
        int q = tid + i * THREADS;
        br[i] = *(const float4*)(Wp + (size_t)(q / KB4) * KD + (q % KB4) * 4);
    }

    u64 acc[TM][TN / 2];
    #pragma unroll
    for (int i = 0; i < TM; i++)
        #pragma unroll
        for (int j = 0; j < TN / 2; j++) acc[i][j] = 0ull;

    for (int kt = 0; kt < KD; kt += BK) {
        // Commit staged registers to smem (transposed: [k][m]).
        #pragma unroll
        for (int i = 0; i < AF4; i++) {
            int q = tid + i * THREADS;
            int r = q / KB4, kc = (q % KB4) * 4;
            As[kc + 0][r] = ar[i].x; As[kc + 1][r] = ar[i].y;
            As[kc + 2][r] = ar[i].z; As[kc + 3][r] = ar[i].w;
        }
        #pragma unroll
        for (int i = 0; i < BF4; i++) {
            int q = tid + i * THREADS;
            int r = q / KB4, kc = (q % KB4) * 4;
            Bs[kc + 0][r] = br[i].x; Bs[kc + 1][r] = br[i].y;
            Bs[kc + 2][r] = br[i].z; Bs[kc + 3][r] = br[i].w;
        }
        __syncthreads();

        // Issue next tile's global loads before compute to hide DRAM/L2 latency.
        if (kt + BK < KD) {
            #pragma unroll
            for (int i = 0; i < AF4; i++) {
                int q = tid + i * THREADS;
                ar[i] = *(const float4*)(Ap + (size_t)(q / KB4) * KD + (kt + BK) + (q % KB4) * 4);
            }
            #pragma unroll
            for (int i = 0; i < BF4; i++) {
                int q = tid + i * THREADS;
                br[i] = *(const float4*)(Wp + (size_t)(q / KB4) * KD + (kt + BK) + (q % KB4) * 4);
            }
        }

        #pragma unroll
        for (int k = 0; k < BK; k++) {
            float4 va0 = *(const float4*)(&As[k][ty * 4]);
            float4 va1 = *(const float4*)(&As[k][BM / 2 + ty * 4]);
            float4 vb0 = *(const float4*)(&Bs[k][tx * 4]);
            float4 vb1 = *(const float4*)(&Bs[k][BN / 2 + tx * 4]);
            u64 a2[TM];
            a2[0] = pack_dup(va0.x); a2[1] = pack_dup(va0.y);
            a2[2] = pack_dup(va0.z); a2[3] = pack_dup(va0.w);
            a2[4] = pack_dup(va1.x); a2[5] = pack_dup(va1.y);
            a2[6] = pack_dup(va1.z); a2[7] = pack_dup(va1.w);
            u64 b2[4];
            b2[0] = pack2(vb0.x, vb0.y); b2[1] = pack2(vb0.z, vb0.w);
            b2[2] = pack2(vb1.x, vb1.y); b2[3] = pack2(vb1.z, vb1.w);
            #pragma unroll
            for (int i = 0; i < TM; i++)
                #pragma unroll
                for (int j = 0; j < 4; j++)
                    ffma2(acc[i][j], a2[i], b2[j]);
        }
        __syncthreads();
    }

    // Epilogue: add bias, store.
    float4 bias0 = *(const float4*)(bias + n0 + tx * 4);
    float4 bias1 = *(const float4*)(bias + n0 + BN / 2 + tx * 4);
    #pragma unroll
    for (int i = 0; i < TM; i++) {
        int row = (i < 4) ? (ty * 4 + i) : (BM / 2 + ty * 4 + (i - 4));
        float* Crow = C + (size_t)(m0 + row) * ND + n0;
        float4 o0, o1;
        unpack2(acc[i][0], o0.x, o0.y); unpack2(acc[i][1], o0.z, o0.w);
        unpack2(acc[i][2], o1.x, o1.y); unpack2(acc[i][3], o1.z, o1.w);
        o0.x += bias0.x; o0.y += bias0.y; o0.z += bias0.z; o0.w += bias0.w;
        o1.x += bias1.x; o1.y += bias1.y; o1.z += bias1.z; o1.w += bias1.w;
        *(float4*)(Crow + tx * 4)          = o0;
        *(float4*)(Crow + BN / 2 + tx * 4) = o1;
    }
}

__device__ __forceinline__ float sigm(float v) { return 1.0f / (1.0f + expf(-v)); }

__device__ __forceinline__ float gate1(float pr, float pu, float xc, float hc, float h) {
    float r = sigm(pr);
    float z = sigm(pu);
    float n = tanhf(xc + r * hc);     // hc already contains bch; xc contains bcx
    return n + z * (h - n);           // == (1-z)*n + z*h
}

// Elementwise GRU gate fusion for one timestep.
__global__ __launch_bounds__(256)
void gru_gate(const float* __restrict__ hprev,
              float* __restrict__ hout,
              float* __restrict__ hlast,   // null except at t = SEQ-1
              int t)
{
    const size_t HN = (size_t)BATCH * ND;
    size_t i = ((size_t)blockIdx.x * blockDim.x + threadIdx.x) * 4;
    if (i >= HN) return;

    const size_t GX = (size_t)MX * ND;
    float4 xr = *(const float4*)(g_gx + 0 * GX + (size_t)t * HN + i);
    float4 xu = *(const float4*)(g_gx + 1 * GX + (size_t)t * HN + i);
    float4 xc = *(const float4*)(g_gx + 2 * GX + (size_t)t * HN + i);
    float4 hr = *(const float4*)(g_gh + 0 * HN + i);
    float4 hu = *(const float4*)(g_gh + 1 * HN + i);
    float4 hc = *(const float4*)(g_gh + 2 * HN + i);
    float4 h  = *(const float4*)(hprev + i);

    float4 o;
    o.x = gate1(xr.x + hr.x, xu.x + hu.x, xc.x, hc.x, h.x);
    o.y = gate1(xr.y + hr.y, xu.y + hu.y, xc.y, hc.y, h.y);
    o.z = gate1(xr.z + hr.z, xu.z + hu.z, xc.z, hc.z, h.z);
    o.w = gate1(xr.w + hr.w, xu.w + hu.w, xc.w, hc.w, h.w);

    *(float4*)(hout + i) = o;
    if (hlast) *(float4*)(hlast + i) = o;
}

extern "C" void kernel_launch(void* const* d_in, const int* in_sizes, int n_in,
                              void* d_out, int out_size)
{
    const float* x   = (const float*)d_in[0];
    const float* h0  = (const float*)d_in[1];
    const float* Wrx = (const float*)d_in[2];
    const float* brx = (const float*)d_in[3];
    const float* Wrh = (const float*)d_in[4];
    const float* brh = (const float*)d_in[5];
    const float* Wux = (const float*)d_in[6];
    const float* bux = (const float*)d_in[7];
    const float* Wuh = (const float*)d_in[8];
    const float* buh = (const float*)d_in[9];
    const float* Wcx = (const float*)d_in[10];
    const float* bcx = (const float*)d_in[11];
    const float* Wch = (const float*)d_in[12];
    const float* bch = (const float*)d_in[13];

    float* out   = (float*)d_out;
    float* hseq  = out;                               // [SEQ][BATCH][ND]
    float* hlast = out + (size_t)SEQ * BATCH * ND;    // [BATCH][ND]

    // Phase 1: all x-projections in one batched GEMM (M = 65536, N = 1024 x 3 gates).
    {
        dim3 grid(MX / 128, ND / 128, 3);
        gemm3<128, 128, 16, 256, true><<<grid, 256>>>(x, Wrx, Wux, Wcx, brx, bux, bcx);
    }

    // Phase 2: sequential recurrence. h_{t-1} is read directly from hseq[t-1].
    dim3 gridH(BATCH / 64, ND / 128, 3);
    const size_t HN = (size_t)BATCH * ND;
    const float* hprev = h0;
    for (int t = 0; t < SEQ; t++) {
        gemm3<64, 128, 16, 128, false><<<gridH, 128>>>(hprev, Wrh, Wuh, Wch, brh, buh, bch);
        float* hout = hseq + (size_t)t * HN;
        gru_gate<<<(int)(HN / 4 / 256), 256>>>(hprev, hout,
                                               (t == SEQ - 1) ? hlast : nullptr, t);
        hprev = hout;
    }
}

// round 2
// speedup vs baseline: 1.2889x; 1.2889x over previous
#include <cuda_runtime.h>
#include <math.h>

#define SEQ    256
#define BATCH  256
#define KD     1024   // C_IN * R_IN
#define ND     1024   // C_OUT * R_OUT
#define MX     (SEQ * BATCH)
#define HN     (BATCH * ND)
#define NCTA   128

// x-projections for all timesteps, per gate: [3][SEQ*BATCH][ND] (768 MB scratch)
static __device__ float g_gx[(size_t)3 * MX * ND];
// grid barrier state
static __device__ unsigned g_bar_count;
static __device__ unsigned g_bar_gen;

typedef unsigned long long u64;

__device__ __forceinline__ u64 pack_dup(float v) {
    u64 r; asm("mov.b64 %0, {%1, %1};" : "=l"(r) : "f"(v)); return r;
}
__device__ __forceinline__ u64 pack2(float lo, float hi) {
    u64 r; asm("mov.b64 %0, {%1, %2};" : "=l"(r) : "f"(lo), "f"(hi)); return r;
}
__device__ __forceinline__ void unpack2(u64 v, float& lo, float& hi) {
    asm("mov.b64 {%0, %1}, %2;" : "=f"(lo), "=f"(hi) : "l"(v));
}
// Packed fp32x2 FMA (sm_100+): 2 FMA lanes/instr -> 128 FMA/cyc/SM.
__device__ __forceinline__ void ffma2(u64& d, u64 a, u64 b) {
    asm("fma.rn.f32x2 %0, %1, %2, %0;" : "+l"(d) : "l"(a), "l"(b));
}

// ============================================================================
// Phase 1: GX[g][m][n] = sum_k x[m][k] * Wg[n][k] + bg[n]   (m = t*BATCH + b)
// Unchanged from round 1 (verified); only IS_GX=true path is used.
// ============================================================================
template<int BM, int BN, int BK, int THREADS>
__global__ __launch_bounds__(THREADS)
void gemm_gx(const float* __restrict__ A,
             const float* __restrict__ W0, const float* __restrict__ W1,
             const float* __restrict__ W2,
             const float* __restrict__ b0, const float* __restrict__ b1,
             const float* __restrict__ b2)
{
    constexpr int TM  = 8, TN = 8;
    constexpr int TX  = BN / TN;
    constexpr int TY  = BM / TM;
    static_assert(TX * TY == THREADS, "thread grid mismatch");
    constexpr int AF4 = BM * BK / 4 / THREADS;
    constexpr int BF4 = BN * BK / 4 / THREADS;
    constexpr int KB4 = BK / 4;

    __shared__ float As[BK][BM + 4];
    __shared__ float Bs[BK][BN + 4];

    const int g = blockIdx.z;
    const float* W    = (g == 0) ? W0 : (g == 1) ? W1 : W2;
    const float* bias = (g == 0) ? b0 : (g == 1) ? b1 : b2;
    float* C = g_gx + (size_t)g * ((size_t)MX * ND);

    const int tid = threadIdx.x;
    const int tx  = tid % TX;
    const int ty  = tid / TX;
    const int m0  = blockIdx.x * BM;
    const int n0  = blockIdx.y * BN;

    const float* Ap = A + (size_t)m0 * KD;
    const float* Wp = W + (size_t)n0 * KD;

    float4 ar[AF4], br[BF4];
    #pragma unroll
    for (int i = 0; i < AF4; i++) {
        int q = tid + i * THREADS;
        ar[i] = *(const float4*)(Ap + (size_t)(q / KB4) * KD + (q % KB4) * 4);
    }
    #pragma unroll
    for (int i = 0; i < BF4; i++) {
        int q = tid + i * THREADS;
        br[i] = *(const float4*)(Wp + (size_t)(q / KB4) * KD + (q % KB4) * 4);
    }

    u64 acc[TM][TN / 2];
    #pragma unroll
    for (int i = 0; i < TM; i++)
        #pragma unroll
        for (int j = 0; j < TN / 2; j++) acc[i][j] = 0ull;

    for (int kt = 0; kt < KD; kt += BK) {
        #pragma unroll
        for (int i = 0; i < AF4; i++) {
            int q = tid + i * THREADS;
            int r = q / KB4, kc = (q % KB4) * 4;
            As[kc + 0][r] = ar[i].x; As[kc + 1][r] = ar[i].y;
            As[kc + 2][r] = ar[i].z; As[kc + 3][r] = ar[i].w;
        }
        #pragma unroll
        for (int i = 0; i < BF4; i++) {
            int q = tid + i * THREADS;
            int r = q / KB4, kc = (q % KB4) * 4;
            Bs[kc + 0][r] = br[i].x; Bs[kc + 1][r] = br[i].y;
            Bs[kc + 2][r] = br[i].z; Bs[kc + 3][r] = br[i].w;
        }
        __syncthreads();

        if (kt + BK < KD) {
            #pragma unroll
            for (int i = 0; i < AF4; i++) {
                int q = tid + i * THREADS;
                ar[i] = *(const float4*)(Ap + (size_t)(q / KB4) * KD + (kt + BK) + (q % KB4) * 4);
            }
            #pragma unroll
            for (int i = 0; i < BF4; i++) {
                int q = tid + i * THREADS;
                br[i] = *(const float4*)(Wp + (size_t)(q / KB4) * KD + (kt + BK) + (q % KB4) * 4);
            }
        }

        #pragma unroll
        for (int k = 0; k < BK; k++) {
            float4 va0 = *(const float4*)(&As[k][ty * 4]);
            float4 va1 = *(const float4*)(&As[k][BM / 2 + ty * 4]);
            float4 vb0 = *(const float4*)(&Bs[k][tx * 4]);
            float4 vb1 = *(const float4*)(&Bs[k][BN / 2 + tx * 4]);
            u64 a2[TM];
            a2[0] = pack_dup(va0.x); a2[1] = pack_dup(va0.y);
            a2[2] = pack_dup(va0.z); a2[3] = pack_dup(va0.w);
            a2[4] = pack_dup(va1.x); a2[5] = pack_dup(va1.y);
            a2[6] = pack_dup(va1.z); a2[7] = pack_dup(va1.w);
            u64 b2[4];
            b2[0] = pack2(vb0.x, vb0.y); b2[1] = pack2(vb0.z, vb0.w);
            b2[2] = pack2(vb1.x, vb1.y); b2[3] = pack2(vb1.z, vb1.w);
            #pragma unroll
            for (int i = 0; i < TM; i++)
                #pragma unroll
                for (int j = 0; j < 4; j++)
                    ffma2(acc[i][j], a2[i], b2[j]);
        }
        __syncthreads();
    }

    float4 bias0 = *(const float4*)(bias + n0 + tx * 4);
    float4 bias1 = *(const float4*)(bias + n0 + BN / 2 + tx * 4);
    #pragma unroll
    for (int i = 0; i < TM; i++) {
        int row = (i < 4) ? (ty * 4 + i) : (BM / 2 + ty * 4 + (i - 4));
        float* Crow = C + (size_t)(m0 + row) * ND + n0;
        float4 o0, o1;
        unpack2(acc[i][0], o0.x, o0.y); unpack2(acc[i][1], o0.z, o0.w);
        unpack2(acc[i][2], o1.x, o1.y); unpack2(acc[i][3], o1.z, o1.w);
        o0.x += bias0.x; o0.y += bias0.y; o0.z += bias0.z; o0.w += bias0.w;
        o1.x += bias1.x; o1.y += bias1.y; o1.z += bias1.z; o1.w += bias1.w;
        *(float4*)(Crow + tx * 4)          = o0;
        *(float4*)(Crow + BN / 2 + tx * 4) = o1;
    }
}

// ============================================================================
// Phase 2: persistent fused recurrence.
// 128 CTAs, 256 threads, ~216 KB dyn smem => 1 CTA/SM, all co-resident.
// CTA c: rows r0 = 128*(c&1) .. +128, n-cols n0 = 16*(c>>1) .. +16, all 3 gates.
// Weights (48 cols x 1024) resident in smem for all 256 steps.
// One software grid barrier per timestep.
// ============================================================================
#define WSTR 1026                       // Ws row stride (floats), pad=2
#define ASTR 18                         // As row stride (floats), BK=16 + 2
#define BKC  16                         // K chunk
#define NCHK (KD / BKC)                 // 64 chunks

__global__ void bar_init_kernel() { g_bar_count = 0; g_bar_gen = 0; }

__device__ __forceinline__ float sigm(float v) { return 1.0f / (1.0f + expf(-v)); }

__global__ __launch_bounds__(256, 1)
void gru_persistent(const float* __restrict__ h0,
                    const float* __restrict__ Wrh, const float* __restrict__ brh,
                    const float* __restrict__ Wuh, const float* __restrict__ buh,
                    const float* __restrict__ Wch, const float* __restrict__ bch,
                    float* __restrict__ hseq, float* __restrict__ hlast)
{
    extern __shared__ float smem[];
    float* Ws = smem;                        // [48][WSTR]
    float* As = Ws + 48 * WSTR;              // [2][128][ASTR]
    float* bs = As + 2 * 128 * ASTR;         // [48]

    const int tid = threadIdx.x;
    const int tx  = tid & 15;                // n-col within group
    const int ty  = tid >> 4;                // row group (8 rows each)
    const int c   = blockIdx.x;
    const int r0  = (c & 1) * 128;
    const int n0  = (c >> 1) * 16;

    // ---- load weights once (48 cols x 1024 k, float2, coalesced) ----
    {
        const float* Wg[3] = { Wrh, Wuh, Wch };
        #pragma unroll 4
        for (int i = 0; i < 96; i++) {
            int q   = tid + i * 256;         // float2 index, 48*512 total
            int j48 = q >> 9;                // 0..47
            int k2  = q & 511;               // float2 within row
            int g   = j48 >> 4;
            int j   = j48 & 15;
            float2 v = *(const float2*)(Wg[g] + (size_t)(n0 + j) * KD + k2 * 2);
            *(float2*)(Ws + j48 * WSTR + k2 * 2) = v;
        }
        if (tid < 48) {
            const float* bg = (tid < 16) ? brh : (tid < 32) ? buh : bch;
            bs[tid] = bg[n0 + (tid & 15)];
        }
    }
    __syncthreads();

    const unsigned gen0 = 0;  // bar_init zeroed it this replay
    u64 acc[3][8];
    #pragma unroll
    for (int g = 0; g < 3; g++)
        #pragma unroll
        for (int r = 0; r < 8; r++) acc[g][r] = 0ull;

    for (int t = 0; t < SEQ; t++) {
        const float* hp = (t == 0) ? h0 : (hseq + (size_t)(t - 1) * HN);

        // ---- prefetch epilogue operands (independent of K loop) ----
        float xg[3][8], hpv[8];
        {
            const int col = n0 + tx;
            #pragma unroll
            for (int r = 0; r < 8; r++) {
                size_t row_g = (size_t)(r0 + ty * 8 + r);
                size_t mrow  = (size_t)t * BATCH + row_g;
                xg[0][r] = g_gx[0 * (size_t)MX * ND + mrow * ND + col];
                xg[1][r] = g_gx[1 * (size_t)MX * ND + mrow * ND + col];
                xg[2][r] = g_gx[2 * (size_t)MX * ND + mrow * ND + col];
                hpv[r]   = hp[row_g * ND + col];
            }
        }

        // ---- h-GEMM over K = 1024 in chunks of 16, double-buffered smem ----
        float2 st[4];
        // prefetch chunk 0
        #pragma unroll
        for (int i = 0; i < 4; i++) {
            int q = tid + i * 256;           // 1024 float2 per chunk
            st[i] = *(const float2*)(hp + (size_t)(r0 + (q >> 3)) * KD + (q & 7) * 2);
        }
        #pragma unroll
        for (int i = 0; i < 4; i++) {
            int q = tid + i * 256;
            *(float2*)(As + 0 * 128 * ASTR + (q >> 3) * ASTR + (q & 7) * 2) = st[i];
        }
        __syncthreads();

        for (int kt = 0; kt < NCHK; kt++) {
            const int cur = kt & 1;
            if (kt + 1 < NCHK) {
                #pragma unroll
                for (int i = 0; i < 4; i++) {
                    int q = tid + i * 256;
                    st[i] = *(const float2*)(hp + (size_t)(r0 + (q >> 3)) * KD
                                             + (kt + 1) * BKC + (q & 7) * 2);
                }
            }
            const float* a_base = As + cur * 128 * ASTR + (ty * 8) * ASTR;
            const float* w_base = Ws + tx * WSTR + kt * BKC;
            #pragma unroll
            for (int kp = 0; kp < 8; kp++) {
                u64 w0 = *(const u64*)(w_base + 0 * 16 * WSTR + 2 * kp);
                u64 w1 = *(const u64*)(w_base + 1 * 16 * WSTR + 2 * kp);
                u64 w2 = *(const u64*)(w_base + 2 * 16 * WSTR + 2 * kp);
                #pragma unroll
                for (int r = 0; r < 8; r++) {
                    u64 h2 = *(const u64*)(a_base + r * ASTR + 2 * kp);
                    ffma2(acc[0][r], h2, w0);
                    ffma2(acc[1][r], h2, w1);
                    ffma2(acc[2][r], h2, w2);
                }
            }
            if (kt + 1 < NCHK) {
                const int nxt = 1 - cur;
                #pragma unroll
                for (int i = 0; i < 4; i++) {
                    int q = tid + i * 256;
                    *(float2*)(As + nxt * 128 * ASTR + (q >> 3) * ASTR + (q & 7) * 2) = st[i];
                }
            }
            __syncthreads();
        }

        // ---- fused gate epilogue ----
        {
            const int col = n0 + tx;
            const float br_ = bs[tx], bu_ = bs[16 + tx], bc_ = bs[32 + tx];
            #pragma unroll
            for (int r = 0; r < 8; r++) {
                float lo, hi, pr, pu, pc;
                unpack2(acc[0][r], lo, hi); pr = lo + hi + br_ + xg[0][r];
                unpack2(acc[1][r], lo, hi); pu = lo + hi + bu_ + xg[1][r];
                unpack2(acc[2][r], lo, hi); pc = lo + hi + bc_;     // h-side c + bch
                acc[0][r] = 0ull; acc[1][r] = 0ull; acc[2][r] = 0ull;

                float rr = sigm(pr);
                float zz = sigm(pu);
                float nn = tanhf(xg[2][r] + rr * pc);               // xg[2] has bcx
                float hn = nn + zz * (hpv[r] - nn);

                size_t row_g = (size_t)(r0 + ty * 8 + r);
                hseq[(size_t)t * HN + row_g * ND + col] = hn;
                if (t == SEQ - 1) hlast[row_g * ND + col] = hn;
            }
        }

        // ---- grid barrier ----
        __syncthreads();
        if (tid == 0) {
            __threadfence();
            unsigned prev = atomicAdd(&g_bar_count, 1u);
            if (prev == NCTA - 1) {
                g_bar_count = 0;
                __threadfence();
                atomicAdd(&g_bar_gen, 1u);
            } else {
                unsigned target = gen0 + (unsigned)t + 1u;
                while (*(volatile unsigned*)&g_bar_gen < target) { __nanosleep(40); }
            }
        }
        __syncthreads();
    }
}

// ============================================================================
extern "C" void kernel_launch(void* const* d_in, const int* in_sizes, int n_in,
                              void* d_out, int out_size)
{
    const float* x   = (const float*)d_in[0];
    const float* h0  = (const float*)d_in[1];
    const float* Wrx = (const float*)d_in[2];
    const float* brx = (const float*)d_in[3];
    const float* Wrh = (const float*)d_in[4];
    const float* brh = (const float*)d_in[5];
    const float* Wux = (const float*)d_in[6];
    const float* bux = (const float*)d_in[7];
    const float* Wuh = (const float*)d_in[8];
    const float* buh = (const float*)d_in[9];
    const float* Wcx = (const float*)d_in[10];
    const float* bcx = (const float*)d_in[11];
    const float* Wch = (const float*)d_in[12];
    const float* bch = (const float*)d_in[13];

    float* out   = (float*)d_out;
    float* hseq  = out;                               // [SEQ][BATCH][ND]
    float* hlast = out + (size_t)SEQ * BATCH * ND;    // [BATCH][ND]

    // Phase 1: x-projections for all timesteps (3 gates batched in grid.z).
    {
        dim3 grid(MX / 128, ND / 128, 3);
        gemm_gx<128, 128, 16, 256><<<grid, 256>>>(x, Wrx, Wux, Wcx, brx, bux, bcx);
    }

    // Phase 2: persistent fused recurrence (single launch for all 256 steps).
    {
        static bool attr_done = false;
        const int smem_bytes = (48 * WSTR + 2 * 128 * ASTR + 48) * 4;
        if (!attr_done) {
            cudaFuncSetAttribute(gru_persistent,
                                 cudaFuncAttributeMaxDynamicSharedMemorySize,
                                 smem_bytes);
            attr_done = true;
        }
        bar_init_kernel<<<1, 1>>>();
        gru_persistent<<<NCTA, 256, smem_bytes>>>(h0, Wrh, brh, Wuh, buh, Wch, bch,
                                                  hseq, hlast);
    }
}